// round 2
// baseline (speedup 1.0000x reference)
#include <cuda_runtime.h>
#include <cstdint>
#include <cstddef>

// ---------------- problem-size constants (fixed bench shapes) ----------------
#define NTOK   8192
#define DMAXC  1024
#define EMAXC  16
#define HMAXC  4096
#define CAPMAX 640
#define RBLKS  (NTOK/8)   // router blocks (8 tokens per 256-thread block)

// ---------------- device scratch (static; allocation-free rule) --------------
__device__ float g_gate[NTOK];
__device__ int   g_eid[NTOK];
__device__ int   g_lst_tok[EMAXC * NTOK];
__device__ float g_lst_gate[EMAXC * NTOK];
__device__ int   g_tok4slot[EMAXC * CAPMAX];
__device__ float g_slotgate[EMAXC * CAPMAX];
__device__ float g_h[(size_t)EMAXC * CAPMAX * HMAXC];   // 160 MB
__device__ float g_pp[RBLKS * 16];
__device__ int   g_pf[RBLKS * 16];
__device__ float g_pz[RBLKS];
__device__ int   g_pn[RBLKS];

// ---------------- init: zero the y region of the output ----------------------
__global__ void init_kernel(float* __restrict__ out, long ytot)
{
    long i4 = (long)blockIdx.x * blockDim.x + threadIdx.x;
    long n4 = ytot >> 2;                        // ytot divisible by 4
    long stride = (long)gridDim.x * blockDim.x;
    float4 z = make_float4(0.f, 0.f, 0.f, 0.f);
    for (; i4 < n4; i4 += stride)
        reinterpret_cast<float4*>(out)[i4] = z;
}

// ---------------- router: logits, noisy gating, loss partials ----------------
// one warp per token; 8 tokens per block
__global__ void __launch_bounds__(256) router_kernel(
    const float* __restrict__ x,
    const int* __restrict__ mask,
    const float* __restrict__ noise,
    const float* __restrict__ Wr,
    int N, int D)
{
    int warp = threadIdx.x >> 5;
    int lane = threadIdx.x & 31;
    int t = blockIdx.x * 8 + warp;

    __shared__ float s_log[8][16];
    __shared__ float s_p[16];
    __shared__ int   s_f[16];
    __shared__ float s_z;
    __shared__ int   s_n;

    if (threadIdx.x < 16) { s_p[threadIdx.x] = 0.f; s_f[threadIdx.x] = 0; }
    if (threadIdx.x == 0) { s_z = 0.f; s_n = 0; }
    __syncthreads();

    if (t < N) {
        // ---- logits_clean = x[t] @ W_router  (all 32 lanes accumulate) ----
        float acc[16];
#pragma unroll
        for (int e = 0; e < 16; ++e) acc[e] = 0.f;
        const float* xr = x + (size_t)t * D;
        for (int d = lane; d < D; d += 32) {
            float xv = xr[d];
            const float* w = Wr + (size_t)d * 16;
#pragma unroll
            for (int e = 0; e < 16; ++e) acc[e] = fmaf(xv, w[e], acc[e]);
        }
#pragma unroll
        for (int e = 0; e < 16; ++e) {
            float v = acc[e];
#pragma unroll
            for (int o = 16; o; o >>= 1) v += __shfl_xor_sync(0xFFFFFFFFu, v, o);
            if (lane == 0) s_log[warp][e] = v;
        }
        __syncwarp();

        // ---- per-token gating: lanes 0..15 own expert e; 16..31 mirror ----
        int e = lane & 15;
        float lc = s_log[warp][e];
        int mk = mask[t] ? 1 : 0;
        float nz = noise[(size_t)t * 16 + e];
        float mult = mk ? (1.0f + (nz * 2.0f - 1.0f) * 0.1f) : 1.0f;
        float ln = lc * mult;

        // noisy: max / lse / argmax over 16-lane groups
        float mx = ln;
#pragma unroll
        for (int o = 8; o; o >>= 1) mx = fmaxf(mx, __shfl_xor_sync(0xFFFFFFFFu, mx, o, 16));
        unsigned bal = __ballot_sync(0xFFFFFFFFu, ln == mx);
        int eid = __ffs(bal) - 1;               // lowest set bit is in lanes 0..15
        float se = expf(ln - mx);
#pragma unroll
        for (int o = 8; o; o >>= 1) se += __shfl_xor_sync(0xFFFFFFFFu, se, o, 16);
        float lse = mx + logf(se);
        float gate = expf(mx - lse);

        // clean: max / lse / argmax / probs
        float mxc = lc;
#pragma unroll
        for (int o = 8; o; o >>= 1) mxc = fmaxf(mxc, __shfl_xor_sync(0xFFFFFFFFu, mxc, o, 16));
        unsigned balc = __ballot_sync(0xFFFFFFFFu, lc == mxc);
        int eidc = __ffs(balc) - 1;
        float sec = expf(lc - mxc);
#pragma unroll
        for (int o = 8; o; o >>= 1) sec += __shfl_xor_sync(0xFFFFFFFFu, sec, o, 16);
        float lsec = mxc + logf(sec);
        float pce = expf(lc - lsec);
        float z = lsec;

        if (lane < 16 && mk) {
            atomicAdd(&s_p[e], pce);
            if (e == eidc) atomicAdd(&s_f[e], 1);
        }
        if (lane == 0) {
            g_gate[t] = gate;
            g_eid[t]  = eid;
            if (mk) { atomicAdd(&s_z, z * z); atomicAdd(&s_n, 1); }
        }
    }
    __syncthreads();
    if (threadIdx.x < 16) {
        g_pp[blockIdx.x * 16 + threadIdx.x] = s_p[threadIdx.x];
        g_pf[blockIdx.x * 16 + threadIdx.x] = s_f[threadIdx.x];
    }
    if (threadIdx.x == 0) { g_pz[blockIdx.x] = s_z; g_pn[blockIdx.x] = s_n; }
}

// ---------------- loss reduce (single block) ----------------------------------
__global__ void loss_reduce_kernel(float* __restrict__ out, int nb, long outsz)
{
    __shared__ float sp[16];
    __shared__ float sf[16];
    __shared__ float szn[2];
    int tid = threadIdx.x;
    if (tid < 16) {
        float s = 0.f; int c = 0;
        for (int b = 0; b < nb; ++b) { s += g_pp[b * 16 + tid]; c += g_pf[b * 16 + tid]; }
        sp[tid] = s; sf[tid] = (float)c;
    }
    if (tid == 16) { float s = 0.f; for (int b = 0; b < nb; ++b) s += g_pz[b]; szn[0] = s; }
    if (tid == 17) { int c = 0;     for (int b = 0; b < nb; ++b) c += g_pn[b]; szn[1] = (float)c; }
    __syncthreads();
    if (tid == 0) {
        float n = szn[1];
        float lb = 0.f;
        for (int e = 0; e < 16; ++e) lb += (sp[e] / n) * (sf[e] / n);
        lb *= 16.0f;
        out[outsz - 2] = lb;
        out[outsz - 1] = szn[0] / n;
    }
}

// ---------------- dispatch: per-expert top-cap by gate (lexsort semantics) ----
__global__ void __launch_bounds__(256) dispatch_kernel(
    const int* __restrict__ mask, int N, int cap)
{
    int e = blockIdx.x;
    int tid = threadIdx.x;
    __shared__ int s_cnt;
    if (tid == 0) s_cnt = 0;
    for (int i = tid; i < cap; i += 256) {
        g_tok4slot[e * cap + i] = -1;
        g_slotgate[e * cap + i] = 0.f;
    }
    __syncthreads();

    for (int t = tid; t < N; t += 256) {
        if (mask[t] && g_eid[t] == e) {
            int i = atomicAdd(&s_cnt, 1);
            g_lst_tok[e * N + i]  = t;
            g_lst_gate[e * N + i] = g_gate[t];
        }
    }
    __syncthreads();
    int cnt = s_cnt;

    for (int i = tid; i < cnt; i += 256) {
        int   ti = g_lst_tok[e * N + i];
        float gi = g_lst_gate[e * N + i];
        int r = 0;
        for (int j = 0; j < cnt; ++j) {
            float gj = g_lst_gate[e * N + j];
            int   tj = g_lst_tok[e * N + j];
            r += (gj > gi) || (gj == gi && tj < ti);
        }
        if (r < cap) {
            g_tok4slot[e * cap + r] = ti;
            g_slotgate[e * cap + r] = gi;
        }
    }
}

// ---------------- FFN GEMM 1: h = relu( gather(x) @ W1[e] ) -------------------
// C[cap,H] per expert; 128x128 block tile, BK=16, 256 thr, 8x8 microtile
__global__ void __launch_bounds__(256) ffn1_kernel(
    const float* __restrict__ x, const float* __restrict__ W1,
    int D, int H, int cap)
{
    const int e  = blockIdx.z;
    const int m0 = blockIdx.y * 128;
    const int n0 = blockIdx.x * 128;
    const float* B = W1 + (size_t)e * D * H;

    __shared__ float As[16][132];
    __shared__ float Bs[16][128];

    const int tid = threadIdx.x;
    float acc[8][8];
#pragma unroll
    for (int i = 0; i < 8; ++i)
#pragma unroll
        for (int j = 0; j < 8; ++j) acc[i][j] = 0.f;

    // per-thread fixed A-load coordinates
    const int am = tid >> 2;            // 0..63 ; second pass adds 64
    const int akq = (tid & 3) * 4;      // 0,4,8,12
    const float* aptr[2]; bool avalid[2];
#pragma unroll
    for (int it = 0; it < 2; ++it) {
        int row = m0 + it * 64 + am;
        int tok = (row < cap) ? g_tok4slot[e * cap + row] : -1;
        avalid[it] = (tok >= 0);
        aptr[it] = avalid[it] ? (x + (size_t)tok * D) : x;
    }
    const int bk = tid >> 5;            // 0..7 ; second pass adds 8
    const int bnq = (tid & 31) * 4;

    for (int kt = 0; kt < D; kt += 16) {
#pragma unroll
        for (int it = 0; it < 2; ++it) {
            float4 v = make_float4(0.f, 0.f, 0.f, 0.f);
            if (avalid[it]) v = *reinterpret_cast<const float4*>(aptr[it] + kt + akq);
            int m = it * 64 + am;
            As[akq + 0][m] = v.x; As[akq + 1][m] = v.y;
            As[akq + 2][m] = v.z; As[akq + 3][m] = v.w;
        }
#pragma unroll
        for (int it = 0; it < 2; ++it) {
            int k = it * 8 + bk;
            *reinterpret_cast<float4*>(&Bs[k][bnq]) =
                *reinterpret_cast<const float4*>(B + (size_t)(kt + k) * H + n0 + bnq);
        }
        __syncthreads();

        const int tm = (tid >> 4) * 8, tn = (tid & 15) * 8;
#pragma unroll
        for (int k = 0; k < 16; ++k) {
            float4 a0 = *reinterpret_cast<const float4*>(&As[k][tm]);
            float4 a1 = *reinterpret_cast<const float4*>(&As[k][tm + 4]);
            float4 b0 = *reinterpret_cast<const float4*>(&Bs[k][tn]);
            float4 b1 = *reinterpret_cast<const float4*>(&Bs[k][tn + 4]);
            float a[8] = {a0.x,a0.y,a0.z,a0.w,a1.x,a1.y,a1.z,a1.w};
            float b[8] = {b0.x,b0.y,b0.z,b0.w,b1.x,b1.y,b1.z,b1.w};
#pragma unroll
            for (int i = 0; i < 8; ++i)
#pragma unroll
                for (int j = 0; j < 8; ++j) acc[i][j] = fmaf(a[i], b[j], acc[i][j]);
        }
        __syncthreads();
    }

    const int tm = (tid >> 4) * 8, tn = (tid & 15) * 8;
#pragma unroll
    for (int i = 0; i < 8; ++i) {
        int row = m0 + tm + i;
        if (row >= cap) continue;
        float* dst = g_h + (size_t)(e * cap + row) * H + n0 + tn;
        float4 v0, v1;
        v0.x = fmaxf(acc[i][0], 0.f); v0.y = fmaxf(acc[i][1], 0.f);
        v0.z = fmaxf(acc[i][2], 0.f); v0.w = fmaxf(acc[i][3], 0.f);
        v1.x = fmaxf(acc[i][4], 0.f); v1.y = fmaxf(acc[i][5], 0.f);
        v1.z = fmaxf(acc[i][6], 0.f); v1.w = fmaxf(acc[i][7], 0.f);
        *reinterpret_cast<float4*>(dst) = v0;
        *reinterpret_cast<float4*>(dst + 4) = v1;
    }
}

// ---------------- FFN GEMM 2: y[tok] = (h @ W2[e]) * gate ---------------------
__global__ void __launch_bounds__(256) ffn2_kernel(
    const float* __restrict__ W2, float* __restrict__ y,
    int D, int H, int cap)
{
    const int e  = blockIdx.z;
    const int m0 = blockIdx.y * 128;
    const int n0 = blockIdx.x * 128;
    const float* B = W2 + (size_t)e * H * D;

    __shared__ float As[16][132];
    __shared__ float Bs[16][128];

    const int tid = threadIdx.x;
    float acc[8][8];
#pragma unroll
    for (int i = 0; i < 8; ++i)
#pragma unroll
        for (int j = 0; j < 8; ++j) acc[i][j] = 0.f;

    const int am = tid >> 2;
    const int akq = (tid & 3) * 4;
    const float* aptr[2]; bool avalid[2];
#pragma unroll
    for (int it = 0; it < 2; ++it) {
        int row = m0 + it * 64 + am;
        avalid[it] = (row < cap);
        aptr[it] = avalid[it] ? (g_h + (size_t)(e * cap + row) * H) : g_h;
    }
    const int bk = tid >> 5;
    const int bnq = (tid & 31) * 4;

    for (int kt = 0; kt < H; kt += 16) {
#pragma unroll
        for (int it = 0; it < 2; ++it) {
            float4 v = make_float4(0.f, 0.f, 0.f, 0.f);
            if (avalid[it]) v = *reinterpret_cast<const float4*>(aptr[it] + kt + akq);
            int m = it * 64 + am;
            As[akq + 0][m] = v.x; As[akq + 1][m] = v.y;
            As[akq + 2][m] = v.z; As[akq + 3][m] = v.w;
        }
#pragma unroll
        for (int it = 0; it < 2; ++it) {
            int k = it * 8 + bk;
            *reinterpret_cast<float4*>(&Bs[k][bnq]) =
                *reinterpret_cast<const float4*>(B + (size_t)(kt + k) * D + n0 + bnq);
        }
        __syncthreads();

        const int tm = (tid >> 4) * 8, tn = (tid & 15) * 8;
#pragma unroll
        for (int k = 0; k < 16; ++k) {
            float4 a0 = *reinterpret_cast<const float4*>(&As[k][tm]);
            float4 a1 = *reinterpret_cast<const float4*>(&As[k][tm + 4]);
            float4 b0 = *reinterpret_cast<const float4*>(&Bs[k][tn]);
            float4 b1 = *reinterpret_cast<const float4*>(&Bs[k][tn + 4]);
            float a[8] = {a0.x,a0.y,a0.z,a0.w,a1.x,a1.y,a1.z,a1.w};
            float b[8] = {b0.x,b0.y,b0.z,b0.w,b1.x,b1.y,b1.z,b1.w};
#pragma unroll
            for (int i = 0; i < 8; ++i)
#pragma unroll
                for (int j = 0; j < 8; ++j) acc[i][j] = fmaf(a[i], b[j], acc[i][j]);
        }
        __syncthreads();
    }

    const int tm = (tid >> 4) * 8, tn = (tid & 15) * 8;
#pragma unroll
    for (int i = 0; i < 8; ++i) {
        int row = m0 + tm + i;
        if (row >= cap) continue;
        int slot = e * cap + row;
        int tok = g_tok4slot[slot];
        if (tok < 0) continue;
        float gsc = g_slotgate[slot];
        float* dst = y + (size_t)tok * D + n0 + tn;
        float4 v0, v1;
        v0.x = acc[i][0] * gsc; v0.y = acc[i][1] * gsc;
        v0.z = acc[i][2] * gsc; v0.w = acc[i][3] * gsc;
        v1.x = acc[i][4] * gsc; v1.y = acc[i][5] * gsc;
        v1.z = acc[i][6] * gsc; v1.w = acc[i][7] * gsc;
        *reinterpret_cast<float4*>(dst) = v0;
        *reinterpret_cast<float4*>(dst + 4) = v1;
    }
}

// ---------------- launch --------------------------------------------------------
extern "C" void kernel_launch(void* const* d_in, const int* in_sizes, int n_in,
                              void* d_out, int out_size)
{
    const float* x     = (const float*)d_in[0];
    const int*   mask  = (const int*)d_in[1];
    const float* noise = (const float*)d_in[2];
    const float* Wr    = (const float*)d_in[3];
    const float* W1    = (const float*)d_in[4];
    const float* W2    = (const float*)d_in[5];
    float*       out   = (float*)d_out;

    const int  N = in_sizes[1];                       // 8192
    const int  D = in_sizes[0] / N;                   // 1024
    const int  E = in_sizes[2] / N;                   // 16
    const int  H = (int)((long)in_sizes[4] / ((long)E * D));   // 4096
    const int  cap = (int)((long)N * 5 / (4 * E));    // 640 (== int(N*1.25/E))
    const long ytot = (long)N * D;

    // 1) zero y
    init_kernel<<<(unsigned)((ytot / 4 + 255) / 256), 256>>>(out, ytot);
    // 2) router + loss partials
    router_kernel<<<N / 8, 256>>>(x, mask, noise, Wr, N, D);
    // 3) loss scalars
    loss_reduce_kernel<<<1, 32>>>(out, N / 8, (long)out_size);
    // 4) capacity dispatch
    dispatch_kernel<<<E, 256>>>(mask, N, cap);
    // 5) expert FFN
    dim3 g1(H / 128, (cap + 127) / 128, E);
    ffn1_kernel<<<g1, 256>>>(x, W1, D, H, cap);
    dim3 g2(D / 128, (cap + 127) / 128, E);
    ffn2_kernel<<<g2, 256>>>(W2, out, D, H, cap);
}

// round 3
// speedup vs baseline: 1.0030x; 1.0030x over previous
#include <cuda_runtime.h>
#include <cstdint>
#include <cstddef>

// ---------------- problem-size constants (fixed bench shapes) ----------------
#define NTOK   8192
#define DMAXC  1024
#define EMAXC  16
#define HMAXC  4096
#define CAPMAX 640
#define RBLKS  (NTOK/8)   // router blocks (8 tokens per 256-thread block)

// ---------------- device scratch (static; allocation-free rule) --------------
__device__ float g_gate[NTOK];
__device__ int   g_eid[NTOK];
__device__ int   g_lst_tok[EMAXC * NTOK];
__device__ float g_lst_gate[EMAXC * NTOK];
__device__ int   g_tok4slot[EMAXC * CAPMAX];
__device__ float g_slotgate[EMAXC * CAPMAX];
__device__ float g_h[(size_t)EMAXC * CAPMAX * HMAXC];   // 160 MB
__device__ float g_pp[RBLKS * 16];
__device__ int   g_pf[RBLKS * 16];
__device__ float g_pz[RBLKS];
__device__ int   g_pn[RBLKS];

// ---------------- init: zero the y region of the output ----------------------
__global__ void init_kernel(float* __restrict__ out, long ytot)
{
    long i4 = (long)blockIdx.x * blockDim.x + threadIdx.x;
    long n4 = ytot >> 2;                        // ytot divisible by 4
    long stride = (long)gridDim.x * blockDim.x;
    float4 z = make_float4(0.f, 0.f, 0.f, 0.f);
    for (; i4 < n4; i4 += stride)
        reinterpret_cast<float4*>(out)[i4] = z;
}

// ---------------- router: logits, noisy gating, loss partials ----------------
// one warp per token; 8 tokens per block
__global__ void __launch_bounds__(256) router_kernel(
    const float* __restrict__ x,
    const int* __restrict__ mask,
    const float* __restrict__ noise,
    const float* __restrict__ Wr,
    int N, int D)
{
    int warp = threadIdx.x >> 5;
    int lane = threadIdx.x & 31;
    int t = blockIdx.x * 8 + warp;

    __shared__ float s_log[8][16];
    __shared__ float s_p[16];
    __shared__ int   s_f[16];
    __shared__ float s_z;
    __shared__ int   s_n;

    if (threadIdx.x < 16) { s_p[threadIdx.x] = 0.f; s_f[threadIdx.x] = 0; }
    if (threadIdx.x == 0) { s_z = 0.f; s_n = 0; }
    __syncthreads();

    if (t < N) {
        // ---- logits_clean = x[t] @ W_router  (all 32 lanes accumulate) ----
        float acc[16];
#pragma unroll
        for (int e = 0; e < 16; ++e) acc[e] = 0.f;
        const float* xr = x + (size_t)t * D;
        for (int d = lane; d < D; d += 32) {
            float xv = xr[d];
            const float* w = Wr + (size_t)d * 16;
#pragma unroll
            for (int e = 0; e < 16; ++e) acc[e] = fmaf(xv, w[e], acc[e]);
        }
#pragma unroll
        for (int e = 0; e < 16; ++e) {
            float v = acc[e];
#pragma unroll
            for (int o = 16; o; o >>= 1) v += __shfl_xor_sync(0xFFFFFFFFu, v, o);
            if (lane == 0) s_log[warp][e] = v;
        }
        __syncwarp();

        // ---- per-token gating: lanes 0..15 own expert e; 16..31 mirror ----
        int e = lane & 15;
        float lc = s_log[warp][e];
        int mk = mask[t] ? 1 : 0;
        float nz = noise[(size_t)t * 16 + e];
        float mult = mk ? (1.0f + (nz * 2.0f - 1.0f) * 0.1f) : 1.0f;
        float ln = lc * mult;

        // noisy: max / lse / argmax over 16-lane groups
        float mx = ln;
#pragma unroll
        for (int o = 8; o; o >>= 1) mx = fmaxf(mx, __shfl_xor_sync(0xFFFFFFFFu, mx, o, 16));
        unsigned bal = __ballot_sync(0xFFFFFFFFu, ln == mx);
        int eid = __ffs(bal) - 1;               // lowest set bit is in lanes 0..15
        float se = expf(ln - mx);
#pragma unroll
        for (int o = 8; o; o >>= 1) se += __shfl_xor_sync(0xFFFFFFFFu, se, o, 16);
        float lse = mx + logf(se);
        float gate = expf(mx - lse);

        // clean: max / lse / argmax / probs
        float mxc = lc;
#pragma unroll
        for (int o = 8; o; o >>= 1) mxc = fmaxf(mxc, __shfl_xor_sync(0xFFFFFFFFu, mxc, o, 16));
        unsigned balc = __ballot_sync(0xFFFFFFFFu, lc == mxc);
        int eidc = __ffs(balc) - 1;
        float sec = expf(lc - mxc);
#pragma unroll
        for (int o = 8; o; o >>= 1) sec += __shfl_xor_sync(0xFFFFFFFFu, sec, o, 16);
        float lsec = mxc + logf(sec);
        float pce = expf(lc - lsec);
        float z = lsec;

        if (lane < 16 && mk) {
            atomicAdd(&s_p[e], pce);
            if (e == eidc) atomicAdd(&s_f[e], 1);
        }
        if (lane == 0) {
            g_gate[t] = gate;
            g_eid[t]  = eid;
            if (mk) { atomicAdd(&s_z, z * z); atomicAdd(&s_n, 1); }
        }
    }
    __syncthreads();
    if (threadIdx.x < 16) {
        g_pp[blockIdx.x * 16 + threadIdx.x] = s_p[threadIdx.x];
        g_pf[blockIdx.x * 16 + threadIdx.x] = s_f[threadIdx.x];
    }
    if (threadIdx.x == 0) { g_pz[blockIdx.x] = s_z; g_pn[blockIdx.x] = s_n; }
}

// ---------------- loss reduce (single block) ----------------------------------
__global__ void loss_reduce_kernel(float* __restrict__ out, int nb, long outsz)
{
    __shared__ float sp[16];
    __shared__ float sf[16];
    __shared__ float szn[2];
    int tid = threadIdx.x;
    if (tid < 16) {
        float s = 0.f; int c = 0;
        for (int b = 0; b < nb; ++b) { s += g_pp[b * 16 + tid]; c += g_pf[b * 16 + tid]; }
        sp[tid] = s; sf[tid] = (float)c;
    }
    if (tid == 16) { float s = 0.f; for (int b = 0; b < nb; ++b) s += g_pz[b]; szn[0] = s; }
    if (tid == 17) { int c = 0;     for (int b = 0; b < nb; ++b) c += g_pn[b]; szn[1] = (float)c; }
    __syncthreads();
    if (tid == 0) {
        float n = szn[1];
        float lb = 0.f;
        for (int e = 0; e < 16; ++e) lb += (sp[e] / n) * (sf[e] / n);
        lb *= 16.0f;
        out[outsz - 2] = lb;
        out[outsz - 1] = szn[0] / n;
    }
}

// ---------------- dispatch: per-expert top-cap by gate (lexsort semantics) ----
__global__ void __launch_bounds__(256) dispatch_kernel(
    const int* __restrict__ mask, int N, int cap)
{
    int e = blockIdx.x;
    int tid = threadIdx.x;
    __shared__ int s_cnt;
    if (tid == 0) s_cnt = 0;
    for (int i = tid; i < cap; i += 256) {
        g_tok4slot[e * cap + i] = -1;
        g_slotgate[e * cap + i] = 0.f;
    }
    __syncthreads();

    for (int t = tid; t < N; t += 256) {
        if (mask[t] && g_eid[t] == e) {
            int i = atomicAdd(&s_cnt, 1);
            g_lst_tok[e * N + i]  = t;
            g_lst_gate[e * N + i] = g_gate[t];
        }
    }
    __syncthreads();
    int cnt = s_cnt;

    for (int i = tid; i < cnt; i += 256) {
        int   ti = g_lst_tok[e * N + i];
        float gi = g_lst_gate[e * N + i];
        int r = 0;
        for (int j = 0; j < cnt; ++j) {
            float gj = g_lst_gate[e * N + j];
            int   tj = g_lst_tok[e * N + j];
            r += (gj > gi) || (gj == gi && tj < ti);
        }
        if (r < cap) {
            g_tok4slot[e * cap + r] = ti;
            g_slotgate[e * cap + r] = gi;
        }
    }
}

// ---------------- FFN GEMM 1: h = relu( gather(x) @ W1[e] ) -------------------
// C[cap,H] per expert; 128x128 block tile, BK=16, 256 thr, 8x8 microtile
__global__ void __launch_bounds__(256) ffn1_kernel(
    const float* __restrict__ x, const float* __restrict__ W1,
    int D, int H, int cap)
{
    const int e  = blockIdx.z;
    const int m0 = blockIdx.y * 128;
    const int n0 = blockIdx.x * 128;
    const float* B = W1 + (size_t)e * D * H;

    __shared__ float As[16][132];
    __shared__ float Bs[16][128];

    const int tid = threadIdx.x;
    float acc[8][8];
#pragma unroll
    for (int i = 0; i < 8; ++i)
#pragma unroll
        for (int j = 0; j < 8; ++j) acc[i][j] = 0.f;

    // per-thread fixed A-load coordinates
    const int am = tid >> 2;            // 0..63 ; second pass adds 64
    const int akq = (tid & 3) * 4;      // 0,4,8,12
    const float* aptr[2]; bool avalid[2];
#pragma unroll
    for (int it = 0; it < 2; ++it) {
        int row = m0 + it * 64 + am;
        int tok = (row < cap) ? g_tok4slot[e * cap + row] : -1;
        avalid[it] = (tok >= 0);
        aptr[it] = avalid[it] ? (x + (size_t)tok * D) : x;
    }
    const int bk = tid >> 5;            // 0..7 ; second pass adds 8
    const int bnq = (tid & 31) * 4;

    for (int kt = 0; kt < D; kt += 16) {
#pragma unroll
        for (int it = 0; it < 2; ++it) {
            float4 v = make_float4(0.f, 0.f, 0.f, 0.f);
            if (avalid[it]) v = *reinterpret_cast<const float4*>(aptr[it] + kt + akq);
            int m = it * 64 + am;
            As[akq + 0][m] = v.x; As[akq + 1][m] = v.y;
            As[akq + 2][m] = v.z; As[akq + 3][m] = v.w;
        }
#pragma unroll
        for (int it = 0; it < 2; ++it) {
            int k = it * 8 + bk;
            *reinterpret_cast<float4*>(&Bs[k][bnq]) =
                *reinterpret_cast<const float4*>(B + (size_t)(kt + k) * H + n0 + bnq);
        }
        __syncthreads();

        const int tm = (tid >> 4) * 8, tn = (tid & 15) * 8;
#pragma unroll
        for (int k = 0; k < 16; ++k) {
            float4 a0 = *reinterpret_cast<const float4*>(&As[k][tm]);
            float4 a1 = *reinterpret_cast<const float4*>(&As[k][tm + 4]);
            float4 b0 = *reinterpret_cast<const float4*>(&Bs[k][tn]);
            float4 b1 = *reinterpret_cast<const float4*>(&Bs[k][tn + 4]);
            float a[8] = {a0.x,a0.y,a0.z,a0.w,a1.x,a1.y,a1.z,a1.w};
            float b[8] = {b0.x,b0.y,b0.z,b0.w,b1.x,b1.y,b1.z,b1.w};
#pragma unroll
            for (int i = 0; i < 8; ++i)
#pragma unroll
                for (int j = 0; j < 8; ++j) acc[i][j] = fmaf(a[i], b[j], acc[i][j]);
        }
        __syncthreads();
    }

    const int tm = (tid >> 4) * 8, tn = (tid & 15) * 8;
#pragma unroll
    for (int i = 0; i < 8; ++i) {
        int row = m0 + tm + i;
        if (row >= cap) continue;
        float* dst = g_h + (size_t)(e * cap + row) * H + n0 + tn;
        float4 v0, v1;
        v0.x = fmaxf(acc[i][0], 0.f); v0.y = fmaxf(acc[i][1], 0.f);
        v0.z = fmaxf(acc[i][2], 0.f); v0.w = fmaxf(acc[i][3], 0.f);
        v1.x = fmaxf(acc[i][4], 0.f); v1.y = fmaxf(acc[i][5], 0.f);
        v1.z = fmaxf(acc[i][6], 0.f); v1.w = fmaxf(acc[i][7], 0.f);
        *reinterpret_cast<float4*>(dst) = v0;
        *reinterpret_cast<float4*>(dst + 4) = v1;
    }
}

// ---------------- FFN GEMM 2: y[tok] = (h @ W2[e]) * gate ---------------------
__global__ void __launch_bounds__(256) ffn2_kernel(
    const float* __restrict__ W2, float* __restrict__ y,
    int D, int H, int cap)
{
    const int e  = blockIdx.z;
    const int m0 = blockIdx.y * 128;
    const int n0 = blockIdx.x * 128;
    const float* B = W2 + (size_t)e * H * D;

    __shared__ float As[16][132];
    __shared__ float Bs[16][128];

    const int tid = threadIdx.x;
    float acc[8][8];
#pragma unroll
    for (int i = 0; i < 8; ++i)
#pragma unroll
        for (int j = 0; j < 8; ++j) acc[i][j] = 0.f;

    const int am = tid >> 2;
    const int akq = (tid & 3) * 4;
    const float* aptr[2]; bool avalid[2];
#pragma unroll
    for (int it = 0; it < 2; ++it) {
        int row = m0 + it * 64 + am;
        avalid[it] = (row < cap);
        aptr[it] = avalid[it] ? (g_h + (size_t)(e * cap + row) * H) : g_h;
    }
    const int bk = tid >> 5;
    const int bnq = (tid & 31) * 4;

    for (int kt = 0; kt < H; kt += 16) {
#pragma unroll
        for (int it = 0; it < 2; ++it) {
            float4 v = make_float4(0.f, 0.f, 0.f, 0.f);
            if (avalid[it]) v = *reinterpret_cast<const float4*>(aptr[it] + kt + akq);
            int m = it * 64 + am;
            As[akq + 0][m] = v.x; As[akq + 1][m] = v.y;
            As[akq + 2][m] = v.z; As[akq + 3][m] = v.w;
        }
#pragma unroll
        for (int it = 0; it < 2; ++it) {
            int k = it * 8 + bk;
            *reinterpret_cast<float4*>(&Bs[k][bnq]) =
                *reinterpret_cast<const float4*>(B + (size_t)(kt + k) * D + n0 + bnq);
        }
        __syncthreads();

        const int tm = (tid >> 4) * 8, tn = (tid & 15) * 8;
#pragma unroll
        for (int k = 0; k < 16; ++k) {
            float4 a0 = *reinterpret_cast<const float4*>(&As[k][tm]);
            float4 a1 = *reinterpret_cast<const float4*>(&As[k][tm + 4]);
            float4 b0 = *reinterpret_cast<const float4*>(&Bs[k][tn]);
            float4 b1 = *reinterpret_cast<const float4*>(&Bs[k][tn + 4]);
            float a[8] = {a0.x,a0.y,a0.z,a0.w,a1.x,a1.y,a1.z,a1.w};
            float b[8] = {b0.x,b0.y,b0.z,b0.w,b1.x,b1.y,b1.z,b1.w};
#pragma unroll
            for (int i = 0; i < 8; ++i)
#pragma unroll
                for (int j = 0; j < 8; ++j) acc[i][j] = fmaf(a[i], b[j], acc[i][j]);
        }
        __syncthreads();
    }

    const int tm = (tid >> 4) * 8, tn = (tid & 15) * 8;
#pragma unroll
    for (int i = 0; i < 8; ++i) {
        int row = m0 + tm + i;
        if (row >= cap) continue;
        int slot = e * cap + row;
        int tok = g_tok4slot[slot];
        if (tok < 0) continue;
        float gsc = g_slotgate[slot];
        float* dst = y + (size_t)tok * D + n0 + tn;
        float4 v0, v1;
        v0.x = acc[i][0] * gsc; v0.y = acc[i][1] * gsc;
        v0.z = acc[i][2] * gsc; v0.w = acc[i][3] * gsc;
        v1.x = acc[i][4] * gsc; v1.y = acc[i][5] * gsc;
        v1.z = acc[i][6] * gsc; v1.w = acc[i][7] * gsc;
        *reinterpret_cast<float4*>(dst) = v0;
        *reinterpret_cast<float4*>(dst + 4) = v1;
    }
}

// ---------------- launch --------------------------------------------------------
extern "C" void kernel_launch(void* const* d_in, const int* in_sizes, int n_in,
                              void* d_out, int out_size)
{
    const float* x     = (const float*)d_in[0];
    const int*   mask  = (const int*)d_in[1];
    const float* noise = (const float*)d_in[2];
    const float* Wr    = (const float*)d_in[3];
    const float* W1    = (const float*)d_in[4];
    const float* W2    = (const float*)d_in[5];
    float*       out   = (float*)d_out;

    const int  N = in_sizes[1];                       // 8192
    const int  D = in_sizes[0] / N;                   // 1024
    const int  E = in_sizes[2] / N;                   // 16
    const int  H = (int)((long)in_sizes[4] / ((long)E * D));   // 4096
    const int  cap = (int)((long)N * 5 / (4 * E));    // 640 (== int(N*1.25/E))
    const long ytot = (long)N * D;

    // 1) zero y
    init_kernel<<<(unsigned)((ytot / 4 + 255) / 256), 256>>>(out, ytot);
    // 2) router + loss partials
    router_kernel<<<N / 8, 256>>>(x, mask, noise, Wr, N, D);
    // 3) loss scalars
    loss_reduce_kernel<<<1, 32>>>(out, N / 8, (long)out_size);
    // 4) capacity dispatch
    dispatch_kernel<<<E, 256>>>(mask, N, cap);
    // 5) expert FFN
    dim3 g1(H / 128, (cap + 127) / 128, E);
    ffn1_kernel<<<g1, 256>>>(x, W1, D, H, cap);
    dim3 g2(D / 128, (cap + 127) / 128, E);
    ffn2_kernel<<<g2, 256>>>(W2, out, D, H, cap);
}

// round 5
// speedup vs baseline: 2.3323x; 2.3253x over previous
#include <cuda_runtime.h>
#include <cstdint>
#include <cstddef>

typedef unsigned short ushort_t;

#define NTOK 8192
#define EEXP 16
#define CAPS 640
#define RBLKS (NTOK/8)

// ---------------- static device scratch ----------------
__device__ ushort_t g_xhi[(size_t)NTOK * 1024];
__device__ ushort_t g_xlo[(size_t)NTOK * 1024];
__device__ ushort_t g_w1hi[(size_t)EEXP * 1024 * 4096];
__device__ ushort_t g_w1lo[(size_t)EEXP * 1024 * 4096];
__device__ ushort_t g_w2hi[(size_t)EEXP * 4096 * 1024];
__device__ ushort_t g_w2lo[(size_t)EEXP * 4096 * 1024];
__device__ ushort_t g_hhi[(size_t)EEXP * CAPS * 4096];
__device__ ushort_t g_hlo[(size_t)EEXP * CAPS * 4096];
__device__ float g_gate[NTOK];
__device__ int   g_eid[NTOK];
__device__ int   g_tok4slot[EEXP * CAPS];
__device__ float g_slotgate[EEXP * CAPS];
__device__ float g_pp[RBLKS * 16];
__device__ int   g_pf[RBLKS * 16];
__device__ float g_pz[RBLKS];
__device__ int   g_pn[RBLKS];

// ---------------- helpers ----------------
__device__ __forceinline__ uint32_t f2bf(float f) {
    uint32_t x = __float_as_uint(f);
    return (x + 0x7FFFu + ((x >> 16) & 1u)) >> 16;
}
__device__ __forceinline__ float bf2f(uint32_t b) { return __uint_as_float(b << 16); }
__device__ __forceinline__ uint32_t smem_u32(const void* p) {
    uint32_t a;
    asm("{ .reg .u64 t; cvta.to.shared.u64 t, %1; cvt.u32.u64 %0, t; }" : "=r"(a) : "l"(p));
    return a;
}
__device__ __forceinline__ void cpa16(uint32_t d, const void* s) {
    asm volatile("cp.async.cg.shared.global [%0], [%1], 16;" :: "r"(d), "l"(s));
}
__device__ __forceinline__ void cp_commit() { asm volatile("cp.async.commit_group;"); }
__device__ __forceinline__ void cp_wait0() { asm volatile("cp.async.wait_group 0;" ::: "memory"); }
__device__ __forceinline__ void cp_wait1() { asm volatile("cp.async.wait_group 1;" ::: "memory"); }
__device__ __forceinline__ void ldsm4(uint32_t* r, uint32_t a) {
    asm volatile("ldmatrix.sync.aligned.m8n8.x4.shared.b16 {%0,%1,%2,%3}, [%4];"
        : "=r"(r[0]), "=r"(r[1]), "=r"(r[2]), "=r"(r[3]) : "r"(a));
}
__device__ __forceinline__ void ldsm4t(uint32_t* r, uint32_t a) {
    asm volatile("ldmatrix.sync.aligned.m8n8.x4.trans.shared.b16 {%0,%1,%2,%3}, [%4];"
        : "=r"(r[0]), "=r"(r[1]), "=r"(r[2]), "=r"(r[3]) : "r"(a));
}
__device__ __forceinline__ void mma16816(float* c, const uint32_t* a, uint32_t b0, uint32_t b1) {
    asm volatile("mma.sync.aligned.m16n8k16.row.col.f32.bf16.bf16.f32 "
        "{%0,%1,%2,%3}, {%4,%5,%6,%7}, {%8,%9}, {%0,%1,%2,%3};"
        : "+f"(c[0]), "+f"(c[1]), "+f"(c[2]), "+f"(c[3])
        : "r"(a[0]), "r"(a[1]), "r"(a[2]), "r"(a[3]), "r"(b0), "r"(b1));
}

// ---------------- init ----------------
__global__ void init_kernel(float* __restrict__ out, long ytot) {
    long i4 = (long)blockIdx.x * blockDim.x + threadIdx.x;
    long n4 = ytot >> 2;
    long stride = (long)gridDim.x * blockDim.x;
    float4 z = make_float4(0.f, 0.f, 0.f, 0.f);
    for (; i4 < n4; i4 += stride) reinterpret_cast<float4*>(out)[i4] = z;
}

// ---------------- bf16 split pack (elementwise) ----------------
__global__ void pack_kernel(const float* __restrict__ in, ushort_t* __restrict__ hi,
                            ushort_t* __restrict__ lo, long n4)
{
    long i = (long)blockIdx.x * blockDim.x + threadIdx.x;
    long stride = (long)gridDim.x * blockDim.x;
    for (; i < n4; i += stride) {
        float4 v = reinterpret_cast<const float4*>(in)[i];
        uint32_t hx = f2bf(v.x), hy = f2bf(v.y), hz = f2bf(v.z), hw = f2bf(v.w);
        uint32_t lx = f2bf(v.x - bf2f(hx)), ly = f2bf(v.y - bf2f(hy));
        uint32_t lz = f2bf(v.z - bf2f(hz)), lw = f2bf(v.w - bf2f(hw));
        reinterpret_cast<uint2*>(hi)[i] = make_uint2(hx | (hy << 16), hz | (hw << 16));
        reinterpret_cast<uint2*>(lo)[i] = make_uint2(lx | (ly << 16), lz | (lw << 16));
    }
}

// ---------------- router ----------------
__global__ void __launch_bounds__(256) router_kernel(
    const float* __restrict__ x, const int* __restrict__ mask,
    const float* __restrict__ noise, const float* __restrict__ Wr, int N, int D)
{
    int warp = threadIdx.x >> 5, lane = threadIdx.x & 31;
    int t = blockIdx.x * 8 + warp;
    __shared__ float s_log[8][16];
    __shared__ float s_p[16]; __shared__ int s_f[16];
    __shared__ float s_z; __shared__ int s_n;
    if (threadIdx.x < 16) { s_p[threadIdx.x] = 0.f; s_f[threadIdx.x] = 0; }
    if (threadIdx.x == 0) { s_z = 0.f; s_n = 0; }
    __syncthreads();
    if (t < N) {
        float acc[16];
#pragma unroll
        for (int e = 0; e < 16; ++e) acc[e] = 0.f;
        const float* xr = x + (size_t)t * D;
        for (int d = lane; d < D; d += 32) {
            float xv = xr[d];
            const float* w = Wr + (size_t)d * 16;
#pragma unroll
            for (int e = 0; e < 16; ++e) acc[e] = fmaf(xv, w[e], acc[e]);
        }
#pragma unroll
        for (int e = 0; e < 16; ++e) {
            float v = acc[e];
#pragma unroll
            for (int o = 16; o; o >>= 1) v += __shfl_xor_sync(0xFFFFFFFFu, v, o);
            if (lane == 0) s_log[warp][e] = v;
        }
        __syncwarp();
        int e = lane & 15;
        float lc = s_log[warp][e];
        int mk = mask[t] ? 1 : 0;
        float nz = noise[(size_t)t * 16 + e];
        float mult = mk ? (1.0f + (nz * 2.0f - 1.0f) * 0.1f) : 1.0f;
        float ln = lc * mult;
        float mx = ln;
#pragma unroll
        for (int o = 8; o; o >>= 1) mx = fmaxf(mx, __shfl_xor_sync(0xFFFFFFFFu, mx, o, 16));
        unsigned bal = __ballot_sync(0xFFFFFFFFu, ln == mx);
        int eid = __ffs(bal) - 1;
        float se = expf(ln - mx);
#pragma unroll
        for (int o = 8; o; o >>= 1) se += __shfl_xor_sync(0xFFFFFFFFu, se, o, 16);
        float lse = mx + logf(se);
        float gate = expf(mx - lse);
        float mxc = lc;
#pragma unroll
        for (int o = 8; o; o >>= 1) mxc = fmaxf(mxc, __shfl_xor_sync(0xFFFFFFFFu, mxc, o, 16));
        unsigned balc = __ballot_sync(0xFFFFFFFFu, lc == mxc);
        int eidc = __ffs(balc) - 1;
        float sec = expf(lc - mxc);
#pragma unroll
        for (int o = 8; o; o >>= 1) sec += __shfl_xor_sync(0xFFFFFFFFu, sec, o, 16);
        float lsec = mxc + logf(sec);
        float pce = expf(lc - lsec);
        if (lane < 16 && mk) {
            atomicAdd(&s_p[e], pce);
            if (e == eidc) atomicAdd(&s_f[e], 1);
        }
        if (lane == 0) {
            g_gate[t] = gate; g_eid[t] = eid;
            if (mk) { atomicAdd(&s_z, lsec * lsec); atomicAdd(&s_n, 1); }
        }
    }
    __syncthreads();
    if (threadIdx.x < 16) {
        g_pp[blockIdx.x * 16 + threadIdx.x] = s_p[threadIdx.x];
        g_pf[blockIdx.x * 16 + threadIdx.x] = s_f[threadIdx.x];
    }
    if (threadIdx.x == 0) { g_pz[blockIdx.x] = s_z; g_pn[blockIdx.x] = s_n; }
}

__global__ void loss_reduce_kernel(float* __restrict__ out, int nb, long outsz) {
    __shared__ float sp[16], sf[16], szn[2];
    int tid = threadIdx.x;
    if (tid < 16) {
        float s = 0.f; int c = 0;
        for (int b = 0; b < nb; ++b) { s += g_pp[b * 16 + tid]; c += g_pf[b * 16 + tid]; }
        sp[tid] = s; sf[tid] = (float)c;
    }
    if (tid == 16) { float s = 0.f; for (int b = 0; b < nb; ++b) s += g_pz[b]; szn[0] = s; }
    if (tid == 17) { int c = 0; for (int b = 0; b < nb; ++b) c += g_pn[b]; szn[1] = (float)c; }
    __syncthreads();
    if (tid == 0) {
        float n = szn[1], lb = 0.f;
        for (int e = 0; e < 16; ++e) lb += (sp[e] / n) * (sf[e] / n);
        out[outsz - 2] = lb * 16.0f;
        out[outsz - 1] = szn[0] / n;
    }
}

// ---------------- dispatch (smem-staged rank) ----------------
__global__ void __launch_bounds__(256) dispatch_kernel(
    const int* __restrict__ mask, int N, int cap)
{
    extern __shared__ char dsm[];
    float* sg = (float*)dsm;
    int*   st = (int*)(dsm + (size_t)N * 4);
    int e = blockIdx.x, tid = threadIdx.x;
    __shared__ int s_cnt;
    if (tid == 0) s_cnt = 0;
    for (int i = tid; i < cap; i += 256) {
        g_tok4slot[e * cap + i] = -1;
        g_slotgate[e * cap + i] = 0.f;
    }
    __syncthreads();
    for (int t = tid; t < N; t += 256) {
        if (mask[t] && g_eid[t] == e) {
            int i = atomicAdd(&s_cnt, 1);
            st[i] = t; sg[i] = g_gate[t];
        }
    }
    __syncthreads();
    int cnt = s_cnt;
    for (int i = tid; i < cnt; i += 256) {
        int ti = st[i]; float gi = sg[i];
        int r = 0;
        for (int j = 0; j < cnt; ++j) {
            float gj = sg[j]; int tj = st[j];
            r += (gj > gi) || (gj == gi && tj < ti);
        }
        if (r < cap) {
            g_tok4slot[e * cap + r] = ti;
            g_slotgate[e * cap + r] = gi;
        }
    }
}

// ---------------- bf16-split tensor-core GEMM (mma.sync path) ----------------
// CTA tile 128m x 128n, BK=32, 8 warps (4m x 2n), warp tile 32x64.
// 3 passes per k-chunk: aHi*bHi + aHi*bLo + aLo*bHi into fp32 acc.
// MODE 0: h = relu(gather(x) @ W1[e]); A from g_x{hi,lo}, B=W1[e] [k=1024][n=4096]
// MODE 1: y = (h @ W2[e]) * gate;      A from g_h{hi,lo}, B=W2[e] [k=4096][n=1024]
#define ABUF_OFF(buf, s) ((buf) * 36864 + (s) * 10240)
#define BBUF_OFF(buf, s) ((buf) * 36864 + 20480 + (s) * 8192)
#define GSMEM 73728

template<int MODE>
__global__ void __launch_bounds__(256, 2) gemm_kernel(
    const float* __restrict__ xunused, float* __restrict__ y, int cap)
{
    const int K   = (MODE == 0) ? 1024 : 4096;
    const int NT  = (MODE == 0) ? 32 : 8;
    const int Nn  = (MODE == 0) ? 4096 : 1024;
    const int NCH = K / 32;

    int b = blockIdx.x;
    const int m  = b % 5; b /= 5;
    const int n  = b % NT;
    const int e  = b / NT;
    const int m0 = m * 128, n0 = n * 128;

    extern __shared__ char smem[];
    const uint32_t sb = smem_u32(smem);
    __shared__ int s_arow[128];

    const int tid = threadIdx.x, wid = tid >> 5, lane = tid & 31;
    const int wm = wid & 3, wn = wid >> 2;

    if (tid < 128) {
        if (MODE == 0) {
            int tok = g_tok4slot[e * cap + m0 + tid];
            s_arow[tid] = (tok >= 0) ? tok : 0;
        } else {
            s_arow[tid] = e * CAPS + m0 + tid;
        }
    }
    __syncthreads();

    const ushort_t* AHI = (MODE == 0) ? g_xhi : g_hhi;
    const ushort_t* ALO = (MODE == 0) ? g_xlo : g_hlo;
    const ushort_t* BHI = ((MODE == 0) ? g_w1hi : g_w2hi) + (size_t)e * K * Nn;
    const ushort_t* BLO = ((MODE == 0) ? g_w1lo : g_w2lo) + (size_t)e * K * Nn;

    // per-thread fixed load coordinates
    const int ar0 = tid >> 2, ac0 = tid & 3;          // A pair 0: row, 16B-chunk
    const int ar1 = (tid + 256) >> 2, ac1 = tid & 3;  // A pair 1
    const int bk0 = tid >> 4, bc0 = tid & 15;         // B pair 0: k-row, 16B-chunk
    const int bk1 = (tid + 256) >> 4, bc1 = tid & 15; // B pair 1
    const ushort_t* aHi0 = AHI + (size_t)s_arow[ar0] * K + ac0 * 8;
    const ushort_t* aLo0 = ALO + (size_t)s_arow[ar0] * K + ac0 * 8;
    const ushort_t* aHi1 = AHI + (size_t)s_arow[ar1] * K + ac1 * 8;
    const ushort_t* aLo1 = ALO + (size_t)s_arow[ar1] * K + ac1 * 8;
    const ushort_t* bHi0 = BHI + (size_t)bk0 * Nn + n0 + bc0 * 8;
    const ushort_t* bLo0 = BLO + (size_t)bk0 * Nn + n0 + bc0 * 8;
    const ushort_t* bHi1 = BHI + (size_t)bk1 * Nn + n0 + bc1 * 8;
    const ushort_t* bLo1 = BLO + (size_t)bk1 * Nn + n0 + bc1 * 8;
    const uint32_t aoff0 = ar0 * 80 + ac0 * 16, aoff1 = ar1 * 80 + ac1 * 16;
    const uint32_t boff0 = bk0 * 256 + ((bc0 ^ (bk0 & 7)) << 4);
    const uint32_t boff1 = bk1 * 256 + ((bc1 ^ (bk1 & 7)) << 4);

    float acc[2][8][4];
#pragma unroll
    for (int i = 0; i < 2; ++i)
#pragma unroll
        for (int j = 0; j < 8; ++j)
#pragma unroll
            for (int q = 0; q < 4; ++q) acc[i][j][q] = 0.f;

    // issue loads for chunk kt into buffer buf
    auto issue = [&](int kt, int buf) {
        const long ka = (long)kt * 32;
        cpa16(sb + ABUF_OFF(buf, 0) + aoff0, aHi0 + ka);
        cpa16(sb + ABUF_OFF(buf, 0) + aoff1, aHi1 + ka);
        cpa16(sb + ABUF_OFF(buf, 1) + aoff0, aLo0 + ka);
        cpa16(sb + ABUF_OFF(buf, 1) + aoff1, aLo1 + ka);
        const long kb = (long)kt * 32 * Nn;
        cpa16(sb + BBUF_OFF(buf, 0) + boff0, bHi0 + kb);
        cpa16(sb + BBUF_OFF(buf, 0) + boff1, bHi1 + kb);
        cpa16(sb + BBUF_OFF(buf, 1) + boff0, bLo0 + kb);
        cpa16(sb + BBUF_OFF(buf, 1) + boff1, bLo1 + kb);
        cp_commit();
    };

    issue(0, 0);

    // ldmatrix per-thread address components
    const uint32_t a_row = (lane & 15), a_kq = (lane >> 4);           // A: row, k-half
    const uint32_t b_kr = (lane & 7) + (lane >> 4) * 8;               // B: k-row within 16... plus ks*16
    const uint32_t b_nc = wn * 8 + ((lane >> 3) & 1);                 // B: n-chunk base (8 bf16)

    for (int kt = 0; kt < NCH; ++kt) {
        const int buf = kt & 1;
        if (kt + 1 < NCH) { issue(kt + 1, buf ^ 1); cp_wait1(); }
        else cp_wait0();
        __syncthreads();

        const uint32_t aH = sb + ABUF_OFF(buf, 0), aL = sb + ABUF_OFF(buf, 1);
        const uint32_t bH = sb + BBUF_OFF(buf, 0), bL = sb + BBUF_OFF(buf, 1);

#pragma unroll
        for (int ks = 0; ks < 2; ++ks) {
            uint32_t fAH[2][4], fAL[2][4];
#pragma unroll
            for (int tm = 0; tm < 2; ++tm) {
                uint32_t ao = (wm * 32 + tm * 16 + a_row) * 80 + (ks * 16 + a_kq * 8) * 2;
                ldsm4(fAH[tm], aH + ao);
                ldsm4(fAL[tm], aL + ao);
            }
            const uint32_t kr = ks * 16 + b_kr;
            const uint32_t krl = kr & 7;
#pragma unroll
            for (int nb = 0; nb < 4; ++nb) {
                uint32_t nc = b_nc + nb * 2;
                uint32_t bo = kr * 256 + ((nc ^ krl) << 4);
                uint32_t fBH[4], fBL[4];
                ldsm4t(fBH, bH + bo);
                ldsm4t(fBL, bL + bo);
#pragma unroll
                for (int tm = 0; tm < 2; ++tm) {
                    mma16816(acc[tm][nb * 2 + 0], fAH[tm], fBH[0], fBH[2]);
                    mma16816(acc[tm][nb * 2 + 1], fAH[tm], fBH[1], fBH[3]);
                    mma16816(acc[tm][nb * 2 + 0], fAH[tm], fBL[0], fBL[2]);
                    mma16816(acc[tm][nb * 2 + 1], fAH[tm], fBL[1], fBL[3]);
                    mma16816(acc[tm][nb * 2 + 0], fAL[tm], fBH[0], fBH[2]);
                    mma16816(acc[tm][nb * 2 + 1], fAL[tm], fBH[1], fBH[3]);
                }
            }
        }
        __syncthreads();
    }

    // ---- epilogue ----
    const int gid = lane >> 2, tig = lane & 3;
#pragma unroll
    for (int tm = 0; tm < 2; ++tm) {
        const int r0 = m0 + wm * 32 + tm * 16 + gid;   // slot row (low)
#pragma unroll
        for (int j = 0; j < 8; ++j) {
            const int col = n0 + wn * 64 + j * 8 + tig * 2;
            if (MODE == 0) {
#pragma unroll
                for (int hh = 0; hh < 2; ++hh) {
                    int row = r0 + hh * 8;
                    float v0 = fmaxf(acc[tm][j][hh * 2 + 0], 0.f);
                    float v1 = fmaxf(acc[tm][j][hh * 2 + 1], 0.f);
                    uint32_t h0 = f2bf(v0), h1 = f2bf(v1);
                    uint32_t l0 = f2bf(v0 - bf2f(h0)), l1 = f2bf(v1 - bf2f(h1));
                    size_t idx = (size_t)(e * CAPS + row) * 4096 + col;
                    *(uint32_t*)(g_hhi + idx) = h0 | (h1 << 16);
                    *(uint32_t*)(g_hlo + idx) = l0 | (l1 << 16);
                }
            } else {
#pragma unroll
                for (int hh = 0; hh < 2; ++hh) {
                    int row = r0 + hh * 8;
                    int slot = e * cap + row;
                    int tok = g_tok4slot[slot];
                    if (tok >= 0) {
                        float g = g_slotgate[slot];
                        float2 v;
                        v.x = acc[tm][j][hh * 2 + 0] * g;
                        v.y = acc[tm][j][hh * 2 + 1] * g;
                        *(float2*)(y + (size_t)tok * 1024 + col) = v;
                    }
                }
            }
        }
    }
}

// ---------------- launch ----------------
extern "C" void kernel_launch(void* const* d_in, const int* in_sizes, int n_in,
                              void* d_out, int out_size)
{
    const float* x     = (const float*)d_in[0];
    const int*   mask  = (const int*)d_in[1];
    const float* noise = (const float*)d_in[2];
    const float* Wr    = (const float*)d_in[3];
    const float* W1    = (const float*)d_in[4];
    const float* W2    = (const float*)d_in[5];
    float*       out   = (float*)d_out;

    const int  N = in_sizes[1];                      // 8192
    const int  D = in_sizes[0] / N;                  // 1024
    const int  E = in_sizes[2] / N;                  // 16
    const int  H = (int)((long)in_sizes[4] / ((long)E * D)); // 4096
    const int  cap = (int)((long)N * 5 / (4 * E));   // 640
    const long ytot = (long)N * D;

    static int attr_done = 0;
    cudaFuncSetAttribute(gemm_kernel<0>, cudaFuncAttributeMaxDynamicSharedMemorySize, GSMEM);
    cudaFuncSetAttribute(gemm_kernel<1>, cudaFuncAttributeMaxDynamicSharedMemorySize, GSMEM);
    cudaFuncSetAttribute(dispatch_kernel, cudaFuncAttributeMaxDynamicSharedMemorySize, 65536);
    (void)attr_done;

    init_kernel<<<(unsigned)((ytot / 4 + 255) / 256), 256>>>(out, ytot);
    router_kernel<<<N / 8, 256>>>(x, mask, noise, Wr, N, D);
    loss_reduce_kernel<<<1, 32>>>(out, N / 8, (long)out_size);
    dispatch_kernel<<<E, 256, (size_t)N * 8>>>(mask, N, cap);

    ushort_t *xhi, *xlo, *w1hi, *w1lo, *w2hi, *w2lo;
    cudaGetSymbolAddress((void**)&xhi, g_xhi);
    cudaGetSymbolAddress((void**)&xlo, g_xlo);
    cudaGetSymbolAddress((void**)&w1hi, g_w1hi);
    cudaGetSymbolAddress((void**)&w1lo, g_w1lo);
    cudaGetSymbolAddress((void**)&w2hi, g_w2hi);
    cudaGetSymbolAddress((void**)&w2lo, g_w2lo);

    pack_kernel<<<2048, 256>>>(x, xhi, xlo, (long)N * D / 4);
    pack_kernel<<<4096, 256>>>(W1, w1hi, w1lo, (long)E * D * H / 4);
    pack_kernel<<<4096, 256>>>(W2, w2hi, w2lo, (long)E * D * H / 4);

    gemm_kernel<0><<<E * (H / 128) * 5, 256, GSMEM>>>(x, out, cap);
    gemm_kernel<1><<<E * (D / 128) * 5, 256, GSMEM>>>(x, out, cap);
}